// round 8
// baseline (speedup 1.0000x reference)
#include <cuda_runtime.h>
#include <cuda_bf16.h>

// Output [B,2] = [p, 1-p], p = sigmoid(evs . fc3_w + fc3_b); evs depends only
// on the 4-qubit circuit (q_params, q_basis). CNN branch is dead code.
//
// R7: minimize both the shfl dependency chain AND issue contention.
//  - 128 threads (4 warps = 1/SMSP, zero issue-slot contention), each warp
//    redundantly computes p; each thread stores 4 float4 output rows.
//  - Layer-0 CNOT chain composed into ONE permutation shfl (computed src).
//  - Layer-1 single-qubit gates fused pairwise into two 4x4 two-qubit gate
//    steps; their coefficients are built from gate entries gathered off the
//    state critical path.
//  - Layer-1 CNOT chain folded into the measurement coefficient index.
// Chained shfl steps on the state path: 7.

__global__ __launch_bounds__(128, 1)
void qhbc_kernel(const float* __restrict__ q_params,  // [2,4,3]
                 const float* __restrict__ q_basis,   // [4,3]
                 const float* __restrict__ fc3_w,     // [1,4]
                 const float* __restrict__ fc3_b,     // [1]
                 float4* __restrict__ out4,           // [B/2] of (p,q,p,q)
                 int n4) {
    const int tid  = threadIdx.x;
    const int lane = tid & 31;
    const int amp  = lane & 15;          // amplitude index (mirrored halves)
    const unsigned FULL = 0xffffffffu;

    // ---- All global loads up front ----
    // Gate slot = lane: 0..3 basis(w), 4..7 layer0(w), 8..11 layer1(w).
    const int w_ = lane & 3;
    const float* ang = (lane < 4) ? (q_basis + w_ * 3)
                                  : (q_params + (lane - 4) * 3);
    const float a0 = (lane < 12) ? ang[0] : 0.f;
    const float a1 = (lane < 12) ? ang[1] : 0.f;
    const float a2 = (lane < 12) ? ang[2] : 0.f;
    const float f0 = fc3_w[0], f1 = fc3_w[1], f2 = fc3_w[2], f3 = fc3_w[3];
    const float bias = fc3_b[0];

    // ---- Measurement coefficient with the FINAL CNOT chain folded in ----
    // CNOT(w): control bit (8>>w), target bit (4>>w), applied to the coef
    // index (permutation invariance of sum_i |amp|^2 * coef).
    int j = amp;
    if (j & 8) j ^= 4;
    if (j & 4) j ^= 2;
    if (j & 2) j ^= 1;
    const float coef = ((j & 8) ? -f0 : f0) + ((j & 4) ? -f1 : f1)
                     + ((j & 2) ? -f2 : f2) + ((j & 1) ? -f3 : f3);

    // ---- Merged SU(2) gate U = Rz*Ry*Rx for this lane's slot ----
    // U = [[u0, u1], [-conj(u1), conj(u0)]]
    float sa, ca, sb, cb, sc, cc;
    __sincosf(0.5f * a0, &sa, &ca);   // Rx
    __sincosf(0.5f * a1, &sb, &cb);   // Ry
    __sincosf(0.5f * a2, &sc, &cc);   // Rz
    const float m00r =  cb * ca, m00i =  sb * sa;
    const float m01r = -sb * ca, m01i = -cb * sa;
    const float gu0r = cc * m00r + sc * m00i;   // u0.r
    const float gu0i = cc * m00i - sc * m00r;   // u0.i
    const float gu1r = cc * m01r + sc * m01i;   // u1.r
    const float gu1i = cc * m01i - sc * m01r;   // u1.i

    // ---- Gather layer-1 gate entries (slots 8..11) — independent of the
    //      state; issues early, overlaps the state chain ----
    const float A0r = __shfl_sync(FULL, gu0r, 8),  A0i = __shfl_sync(FULL, gu0i, 8);
    const float B0r = __shfl_sync(FULL, gu1r, 8),  B0i = __shfl_sync(FULL, gu1i, 8);
    const float A1r = __shfl_sync(FULL, gu0r, 9),  A1i = __shfl_sync(FULL, gu0i, 9);
    const float B1r = __shfl_sync(FULL, gu1r, 9),  B1i = __shfl_sync(FULL, gu1i, 9);
    const float A2r = __shfl_sync(FULL, gu0r, 10), A2i = __shfl_sync(FULL, gu0i, 10);
    const float B2r = __shfl_sync(FULL, gu1r, 10), B2i = __shfl_sync(FULL, gu1i, 10);
    const float A3r = __shfl_sync(FULL, gu0r, 11), A3i = __shfl_sync(FULL, gu0i, 11);
    const float B3r = __shfl_sync(FULL, gu1r, 11), B3i = __shfl_sync(FULL, gu1i, 11);

    // Per-lane row entries for each wire: diag d = r? conj(u0):u0,
    // offdiag o = r? -conj(u1):u1  (sign flips on u0.i and u1.r only).
    const float s0 = (lane & 8) ? -1.f : 1.f;   // wire0 bit
    const float s1 = (lane & 4) ? -1.f : 1.f;   // wire1 bit
    const float s2 = (lane & 2) ? -1.f : 1.f;   // wire2 bit
    const float s3 = (lane & 1) ? -1.f : 1.f;   // wire3 bit
    const float d0r = A0r, d0i = s0 * A0i, o0r = s0 * B0r, o0i = B0i;
    const float d1r = A1r, d1i = s1 * A1i, o1r = s1 * B1r, o1i = B1i;
    const float d2r = A2r, d2i = s2 * A2i, o2r = s2 * B2r, o2i = B2i;
    const float d3r = A3r, d3i = s3 * A3i, o3r = s3 * B3r, o3i = B3i;

    // Two-qubit gate coefficients (complex products), off the state path.
    // Gate(0,1): partners xor {4, 8, 12}
    const float cAAr = d0r*d1r - d0i*d1i, cAAi = d0r*d1i + d0i*d1r; // same
    const float cABr = d0r*o1r - d0i*o1i, cABi = d0r*o1i + d0i*o1r; // ^4
    const float cBAr = o0r*d1r - o0i*d1i, cBAi = o0r*d1i + o0i*d1r; // ^8
    const float cBBr = o0r*o1r - o0i*o1i, cBBi = o0r*o1i + o0i*o1r; // ^12
    // Gate(2,3): partners xor {1, 2, 3}
    const float eAAr = d2r*d3r - d2i*d3i, eAAi = d2r*d3i + d2i*d3r; // same
    const float eABr = d2r*o3r - d2i*o3i, eABi = d2r*o3i + d2i*o3r; // ^1
    const float eBAr = o2r*d3r - o2i*d3i, eBAi = o2r*d3i + o2i*d3r; // ^2
    const float eBBr = o2r*o3r - o2i*o3i, eBBi = o2r*o3i + o2i*o3r; // ^3

    // ---- W_w = U_layer0_w * U_basis_w, column 0 (lanes 0..3 = wire w) ----
    const float x0r = __shfl_down_sync(FULL, gu0r, 4);
    const float x0i = __shfl_down_sync(FULL, gu0i, 4);
    const float x1r = __shfl_down_sync(FULL, gu1r, 4);
    const float x1i = __shfl_down_sync(FULL, gu1i, 4);
    const float W0r = x0r * gu0r - x0i * gu0i - (x1r * gu1r + x1i * gu1i);
    const float W0i = x0r * gu0i + x0i * gu0r - (x1i * gu1r - x1r * gu1i);
    const float W1r = -(x1r * gu0r + x1i * gu0i + x0r * gu1r - x0i * gu1i);
    const float W1i = -(x1r * gu0i - x1i * gu0r - x0r * gu1i - x0i * gu1r);

    // ---- Product state: amp[i] = prod_w Wcol0_w[bit_w(i)] ----
    float cr[4], ci[4];
    #pragma unroll
    for (int w = 0; w < 4; w++) {
        const float t0r = __shfl_sync(FULL, W0r, w);
        const float t0i = __shfl_sync(FULL, W0i, w);
        const float t1r = __shfl_sync(FULL, W1r, w);
        const float t1i = __shfl_sync(FULL, W1i, w);
        const bool b = (amp >> (3 - w)) & 1;
        cr[w] = b ? t1r : t0r;
        ci[w] = b ? t1i : t0i;
    }
    const float p01r = cr[0] * cr[1] - ci[0] * ci[1];
    const float p01i = cr[0] * ci[1] + ci[0] * cr[1];
    const float p23r = cr[2] * cr[3] - ci[2] * ci[3];
    const float p23i = cr[2] * ci[3] + ci[2] * cr[3];
    float sr = p01r * p23r - p01i * p23i;
    float si = p01r * p23i + p01i * p23r;

    // ---- Layer-0 CNOT chain as ONE permutation shfl ----
    // state'[i] = state[sig0(sig1(sig2(i)))], sig_w(i) = i ^ ((i>>1)&(4>>w))
    int src = amp;
    src ^= (src >> 1) & 1;
    src ^= (src >> 1) & 2;
    src ^= (src >> 1) & 4;
    src |= (lane & 16);                 // stay within the mirrored half
    {
        const float tr = __shfl_sync(FULL, sr, src);
        const float ti = __shfl_sync(FULL, si, src);
        sr = tr; si = ti;
    }

    // ---- Fused layer-1 gate on wires (0,1): one chained step ----
    {
        const float p4r  = __shfl_xor_sync(FULL, sr, 4);
        const float p4i  = __shfl_xor_sync(FULL, si, 4);
        const float p8r  = __shfl_xor_sync(FULL, sr, 8);
        const float p8i  = __shfl_xor_sync(FULL, si, 8);
        const float p12r = __shfl_xor_sync(FULL, sr, 12);
        const float p12i = __shfl_xor_sync(FULL, si, 12);
        const float nr = cAAr*sr - cAAi*si + cABr*p4r - cABi*p4i
                       + cBAr*p8r - cBAi*p8i + cBBr*p12r - cBBi*p12i;
        const float ni = cAAr*si + cAAi*sr + cABr*p4i + cABi*p4r
                       + cBAr*p8i + cBAi*p8r + cBBr*p12i + cBBi*p12r;
        sr = nr; si = ni;
    }

    // ---- Fused layer-1 gate on wires (2,3): one chained step ----
    {
        const float p1r = __shfl_xor_sync(FULL, sr, 1);
        const float p1i = __shfl_xor_sync(FULL, si, 1);
        const float p2r = __shfl_xor_sync(FULL, sr, 2);
        const float p2i = __shfl_xor_sync(FULL, si, 2);
        const float p3r = __shfl_xor_sync(FULL, sr, 3);
        const float p3i = __shfl_xor_sync(FULL, si, 3);
        const float nr = eAAr*sr - eAAi*si + eABr*p1r - eABi*p1i
                       + eBAr*p2r - eBAi*p2i + eBBr*p3r - eBBi*p3i;
        const float ni = eAAr*si + eAAi*sr + eABr*p1i + eABi*p1r
                       + eBAr*p2i + eBAi*p2r + eBBr*p3i + eBBi*p3r;
        sr = nr; si = ni;
    }

    // ---- logit sum: butterfly over the mirrored 16-lane halves; every
    //      lane ends with the full sum (no broadcast) ----
    float val = (sr * sr + si * si) * coef;
    val += __shfl_xor_sync(FULL, val, 1);
    val += __shfl_xor_sync(FULL, val, 2);
    val += __shfl_xor_sync(FULL, val, 4);
    val += __shfl_xor_sync(FULL, val, 8);

    const float p = 1.f / (1.f + __expf(-(bias + val)));
    const float q = 1.f - p;
    const float4 v = make_float4(p, q, p, q);

    // ---- 128 threads x 4 independent STG.128 (full MLP) ----
    #pragma unroll
    for (int k = 0; k < 4; k++) {
        const int i = tid + k * 128;
        if (i < n4) out4[i] = v;
    }
}

extern "C" void kernel_launch(void* const* d_in, const int* in_sizes, int n_in,
                              void* d_out, int out_size) {
    // metadata order: 0=x 1=conv1_w 2=conv1_b 3=conv2_w 4=conv2_b 5=fc1_w
    //                 6=fc1_b 7=fc2_w 8=fc2_b 9=q_params 10=q_basis 11=fc3_w 12=fc3_b
    const float* q_params = (const float*)d_in[9];
    const float* q_basis  = (const float*)d_in[10];
    const float* fc3_w    = (const float*)d_in[11];
    const float* fc3_b    = (const float*)d_in[12];
    float4* out4 = (float4*)d_out;
    const int n4 = out_size / 4;   // out_size = B*2 floats; 4 floats per float4

    qhbc_kernel<<<1, 128>>>(q_params, q_basis, fc3_w, fc3_b, out4, n4);
}

// round 9
// speedup vs baseline: 1.0821x; 1.0821x over previous
#include <cuda_runtime.h>
#include <cuda_bf16.h>

// Output [B,2] = [p, 1-p], p = sigmoid(evs . fc3_w + fc3_b); evs depends only
// on the 4-qubit circuit (q_params, q_basis). CNN branch is dead code.
//
// R8: R7's minimal shfl chain (7 chained steps) + R5's store shape
// (512 threads, one float4 per thread) — the block size that benched best.
//  - Pre-CNOT product state built by a 2-level complex product tree.
//  - Layer-0 CNOT chain composed into ONE permutation shfl.
//  - Layer-1 single-qubit gates fused pairwise into two 4x4 two-qubit steps,
//    coefficients built off the state critical path.
//  - Layer-1 CNOT chain folded into the measurement coefficient index.
//  - State mirrored in both 16-lane halves: butterfly leaves the sum in
//    every lane, no broadcast, no smem, no barriers.

__global__ __launch_bounds__(512, 1)
void qhbc_kernel(const float* __restrict__ q_params,  // [2,4,3]
                 const float* __restrict__ q_basis,   // [4,3]
                 const float* __restrict__ fc3_w,     // [1,4]
                 const float* __restrict__ fc3_b,     // [1]
                 float4* __restrict__ out4,           // [B/2] of (p,q,p,q)
                 int n4) {
    const int tid  = threadIdx.x;
    const int lane = tid & 31;
    const int amp  = lane & 15;          // amplitude index (mirrored halves)
    const unsigned FULL = 0xffffffffu;

    // ---- All global loads up front ----
    // Gate slot = lane: 0..3 basis(w), 4..7 layer0(w), 8..11 layer1(w).
    const int w_ = lane & 3;
    const float* ang = (lane < 4) ? (q_basis + w_ * 3)
                                  : (q_params + (lane - 4) * 3);
    const float a0 = (lane < 12) ? ang[0] : 0.f;
    const float a1 = (lane < 12) ? ang[1] : 0.f;
    const float a2 = (lane < 12) ? ang[2] : 0.f;
    const float f0 = fc3_w[0], f1 = fc3_w[1], f2 = fc3_w[2], f3 = fc3_w[3];
    const float bias = fc3_b[0];

    // ---- Measurement coefficient with the FINAL CNOT chain folded in ----
    int j = amp;
    if (j & 8) j ^= 4;
    if (j & 4) j ^= 2;
    if (j & 2) j ^= 1;
    const float coef = ((j & 8) ? -f0 : f0) + ((j & 4) ? -f1 : f1)
                     + ((j & 2) ? -f2 : f2) + ((j & 1) ? -f3 : f3);

    // ---- Merged SU(2) gate U = Rz*Ry*Rx for this lane's slot ----
    // U = [[u0, u1], [-conj(u1), conj(u0)]]
    float sa, ca, sb, cb, sc, cc;
    __sincosf(0.5f * a0, &sa, &ca);   // Rx
    __sincosf(0.5f * a1, &sb, &cb);   // Ry
    __sincosf(0.5f * a2, &sc, &cc);   // Rz
    const float m00r =  cb * ca, m00i =  sb * sa;
    const float m01r = -sb * ca, m01i = -cb * sa;
    const float gu0r = cc * m00r + sc * m00i;   // u0.r
    const float gu0i = cc * m00i - sc * m00r;   // u0.i
    const float gu1r = cc * m01r + sc * m01i;   // u1.r
    const float gu1i = cc * m01i - sc * m01r;   // u1.i

    // ---- Gather layer-1 gate entries (slots 8..11) — off the state path ----
    const float A0r = __shfl_sync(FULL, gu0r, 8),  A0i = __shfl_sync(FULL, gu0i, 8);
    const float B0r = __shfl_sync(FULL, gu1r, 8),  B0i = __shfl_sync(FULL, gu1i, 8);
    const float A1r = __shfl_sync(FULL, gu0r, 9),  A1i = __shfl_sync(FULL, gu0i, 9);
    const float B1r = __shfl_sync(FULL, gu1r, 9),  B1i = __shfl_sync(FULL, gu1i, 9);
    const float A2r = __shfl_sync(FULL, gu0r, 10), A2i = __shfl_sync(FULL, gu0i, 10);
    const float B2r = __shfl_sync(FULL, gu1r, 10), B2i = __shfl_sync(FULL, gu1i, 10);
    const float A3r = __shfl_sync(FULL, gu0r, 11), A3i = __shfl_sync(FULL, gu0i, 11);
    const float B3r = __shfl_sync(FULL, gu1r, 11), B3i = __shfl_sync(FULL, gu1i, 11);

    // Per-lane row entries per wire: diag d = bit? conj(u0):u0,
    // offdiag o = bit? -conj(u1):u1 (sign flips on u0.i, u1.r only).
    const float s0 = (lane & 8) ? -1.f : 1.f;
    const float s1 = (lane & 4) ? -1.f : 1.f;
    const float s2 = (lane & 2) ? -1.f : 1.f;
    const float s3 = (lane & 1) ? -1.f : 1.f;
    const float d0r = A0r, d0i = s0 * A0i, o0r = s0 * B0r, o0i = B0i;
    const float d1r = A1r, d1i = s1 * A1i, o1r = s1 * B1r, o1i = B1i;
    const float d2r = A2r, d2i = s2 * A2i, o2r = s2 * B2r, o2i = B2i;
    const float d3r = A3r, d3i = s3 * A3i, o3r = s3 * B3r, o3i = B3i;

    // Two-qubit fused gate coefficients (complex products), off state path.
    const float cAAr = d0r*d1r - d0i*d1i, cAAi = d0r*d1i + d0i*d1r; // same
    const float cABr = d0r*o1r - d0i*o1i, cABi = d0r*o1i + d0i*o1r; // ^4
    const float cBAr = o0r*d1r - o0i*d1i, cBAi = o0r*d1i + o0i*d1r; // ^8
    const float cBBr = o0r*o1r - o0i*o1i, cBBi = o0r*o1i + o0i*o1r; // ^12
    const float eAAr = d2r*d3r - d2i*d3i, eAAi = d2r*d3i + d2i*d3r; // same
    const float eABr = d2r*o3r - d2i*o3i, eABi = d2r*o3i + d2i*o3r; // ^1
    const float eBAr = o2r*d3r - o2i*d3i, eBAi = o2r*d3i + o2i*d3r; // ^2
    const float eBBr = o2r*o3r - o2i*o3i, eBBi = o2r*o3i + o2i*o3r; // ^3

    // ---- W_w = U_layer0_w * U_basis_w, column 0 (lanes 0..3 = wire w) ----
    const float x0r = __shfl_down_sync(FULL, gu0r, 4);
    const float x0i = __shfl_down_sync(FULL, gu0i, 4);
    const float x1r = __shfl_down_sync(FULL, gu1r, 4);
    const float x1i = __shfl_down_sync(FULL, gu1i, 4);
    const float W0r = x0r * gu0r - x0i * gu0i - (x1r * gu1r + x1i * gu1i);
    const float W0i = x0r * gu0i + x0i * gu0r - (x1i * gu1r - x1r * gu1i);
    const float W1r = -(x1r * gu0r + x1i * gu0i + x0r * gu1r - x0i * gu1i);
    const float W1i = -(x1r * gu0i - x1i * gu0r - x0r * gu1i - x0i * gu1r);

    // ---- Product state: amp[i] = prod_w Wcol0_w[bit_w(i)] ----
    float cr[4], ci[4];
    #pragma unroll
    for (int w = 0; w < 4; w++) {
        const float t0r = __shfl_sync(FULL, W0r, w);
        const float t0i = __shfl_sync(FULL, W0i, w);
        const float t1r = __shfl_sync(FULL, W1r, w);
        const float t1i = __shfl_sync(FULL, W1i, w);
        const bool b = (amp >> (3 - w)) & 1;
        cr[w] = b ? t1r : t0r;
        ci[w] = b ? t1i : t0i;
    }
    const float p01r = cr[0] * cr[1] - ci[0] * ci[1];
    const float p01i = cr[0] * ci[1] + ci[0] * cr[1];
    const float p23r = cr[2] * cr[3] - ci[2] * ci[3];
    const float p23i = cr[2] * ci[3] + ci[2] * cr[3];
    float sr = p01r * p23r - p01i * p23i;
    float si = p01r * p23i + p01i * p23r;

    // ---- Layer-0 CNOT chain as ONE permutation shfl ----
    int src = amp;
    src ^= (src >> 1) & 1;
    src ^= (src >> 1) & 2;
    src ^= (src >> 1) & 4;
    src |= (lane & 16);                 // stay within the mirrored half
    {
        const float tr = __shfl_sync(FULL, sr, src);
        const float ti = __shfl_sync(FULL, si, src);
        sr = tr; si = ti;
    }

    // ---- Fused layer-1 gate on wires (0,1) ----
    {
        const float p4r  = __shfl_xor_sync(FULL, sr, 4);
        const float p4i  = __shfl_xor_sync(FULL, si, 4);
        const float p8r  = __shfl_xor_sync(FULL, sr, 8);
        const float p8i  = __shfl_xor_sync(FULL, si, 8);
        const float p12r = __shfl_xor_sync(FULL, sr, 12);
        const float p12i = __shfl_xor_sync(FULL, si, 12);
        const float nr = cAAr*sr - cAAi*si + cABr*p4r - cABi*p4i
                       + cBAr*p8r - cBAi*p8i + cBBr*p12r - cBBi*p12i;
        const float ni = cAAr*si + cAAi*sr + cABr*p4i + cABi*p4r
                       + cBAr*p8i + cBAi*p8r + cBBr*p12i + cBBi*p12r;
        sr = nr; si = ni;
    }

    // ---- Fused layer-1 gate on wires (2,3) ----
    {
        const float p1r = __shfl_xor_sync(FULL, sr, 1);
        const float p1i = __shfl_xor_sync(FULL, si, 1);
        const float p2r = __shfl_xor_sync(FULL, sr, 2);
        const float p2i = __shfl_xor_sync(FULL, si, 2);
        const float p3r = __shfl_xor_sync(FULL, sr, 3);
        const float p3i = __shfl_xor_sync(FULL, si, 3);
        const float nr = eAAr*sr - eAAi*si + eABr*p1r - eABi*p1i
                       + eBAr*p2r - eBAi*p2i + eBBr*p3r - eBBi*p3i;
        const float ni = eAAr*si + eAAi*sr + eABr*p1i + eABi*p1r
                       + eBAr*p2i + eBAi*p2r + eBBr*p3i + eBBi*p3r;
        sr = nr; si = ni;
    }

    // ---- logit sum: butterfly over the mirrored halves; every lane ends
    //      with the full sum ----
    float val = (sr * sr + si * si) * coef;
    val += __shfl_xor_sync(FULL, val, 1);
    val += __shfl_xor_sync(FULL, val, 2);
    val += __shfl_xor_sync(FULL, val, 4);
    val += __shfl_xor_sync(FULL, val, 8);

    const float p = 1.f / (1.f + __expf(-(bias + val)));
    const float q = 1.f - p;
    const float4 v = make_float4(p, q, p, q);

    // ---- Broadcast store: 512 threads, one float4 (two rows) each ----
    for (int i = tid; i < n4; i += blockDim.x) {
        out4[i] = v;
    }
}

extern "C" void kernel_launch(void* const* d_in, const int* in_sizes, int n_in,
                              void* d_out, int out_size) {
    // metadata order: 0=x 1=conv1_w 2=conv1_b 3=conv2_w 4=conv2_b 5=fc1_w
    //                 6=fc1_b 7=fc2_w 8=fc2_b 9=q_params 10=q_basis 11=fc3_w 12=fc3_b
    const float* q_params = (const float*)d_in[9];
    const float* q_basis  = (const float*)d_in[10];
    const float* fc3_w    = (const float*)d_in[11];
    const float* fc3_b    = (const float*)d_in[12];
    float4* out4 = (float4*)d_out;
    const int n4 = out_size / 4;   // out_size = B*2 floats; 4 floats per float4

    qhbc_kernel<<<1, 512>>>(q_params, q_basis, fc3_w, fc3_b, out4, n4);
}